// round 15
// baseline (speedup 1.0000x reference)
#include <cuda_runtime.h>

#define N   1024
#define T   1024
#define NW  32
#define RCAP 30000

__device__ float    g_dist[N * N];   // exact fp32 distances (final mean)
__device__ unsigned g_mat[N * N];    // (d20 << 10) | col_index
__device__ unsigned g_dmax = 0;      // bits of max distance (positive floats)

// ---- pass 1: exact distances + global max (block-reduced atomic) ----
__global__ void dist_kernel(const float* __restrict__ gt,
                            const float* __restrict__ gen) {
    __shared__ unsigned s_wmax[8];
    const int id = blockIdx.x * blockDim.x + threadIdx.x;
    const int j = id >> 10, i = id & (N - 1);
    const float dx = gen[3 * j]     - gt[3 * i];
    const float dy = gen[3 * j + 1] - gt[3 * i + 1];
    const float dz = gen[3 * j + 2] - gt[3 * i + 2];
    const float d = sqrtf(fmaf(dx, dx, fmaf(dy, dy, dz * dz)));
    g_dist[id] = d;
    unsigned m = __reduce_max_sync(~0u, __float_as_uint(d));  // d>=0: uint==float order
    const int lane = threadIdx.x & 31, wid = threadIdx.x >> 5;
    if (lane == 0) s_wmax[wid] = m;
    __syncthreads();
    if (threadIdx.x < 8) {
        m = s_wmax[threadIdx.x];
        #pragma unroll
        for (int o = 4; o; o >>= 1) m = max(m, __shfl_xor_sync(0xffu, m, o));
        if (threadIdx.x == 0) atomicMax(&g_dmax, m);
    }
}

// ---- pass 2: quantize to 20 bits, pack column index in low 10 bits ----
__global__ void quant_kernel() {
    const int id = blockIdx.x * blockDim.x + threadIdx.x;
    const float dmax = __uint_as_float(g_dmax);
    const float scale = 1048000.0f / dmax;
    const unsigned dq = __float2uint_rn(g_dist[id] * scale);   // <= 1048000
    g_mat[id] = (dq << 10) | (unsigned)(id & (N - 1));
}

// Auction, integer eps-scaling, <=32 fresh-price bidders/round, full restart
// per phase. Tail rounds (nb<=16) split each bidder's row scan across
// 32/nb warps (max 8) and merge slice top-2s. Bids via u64 atomicMax.
__global__ __launch_bounds__(T, 1)
void emd_auction_kernel(float* __restrict__ out) {
    __shared__ __align__(16) unsigned s_pshift[N];    // price << 10
    __shared__ unsigned long long s_slot[N];          // (pnew<<32 | bidder)
    __shared__ short  s_owner[N];                     // object -> bidder (-1 free)
    __shared__ short  s_objof[N];                     // bidder -> object (-1 free)
    __shared__ unsigned short s_q[N];                 // unassigned bidders (sorted)
    __shared__ unsigned s_m1[NW], s_m2[NW];           // slice top-2 buffers
    __shared__ int    s_wcnt[NW], s_wpre[NW];
    __shared__ int    s_nq;
    __shared__ float  s_sum[NW];

    const int t = threadIdx.x, lane = t & 31, wid = t >> 5;

    s_pshift[t] = 0u;
    s_slot[t]   = 0ull;
    s_objof[t]  = -1;
    s_owner[t]  = -1;
    __syncthreads();

    int rounds = 0;
    unsigned eps = 49152u;                            // /4 per phase -> 3

    for (int phase = 0; phase < 8; ++phase) {
        // reset assignment, keep prices
        s_owner[t] = -1; s_objof[t] = -1;
        s_q[t] = (unsigned short)t;
        if (t == 0) s_nq = N;
        __syncthreads();

        while (s_nq > 0 && rounds < RCAP) {
            ++rounds;
            const int nb = min(s_nq, NW);
            // warps per bidder: 1 (nb>=17), else up to 8 (uniform value)
            const int wpb = (nb > 16) ? 1 : ((nb > 8) ? 2 : ((nb > 4) ? 4 : 8));

            if (wpb == 1) {
                // ---- dense path: warp w = bidder s_q[w], full-row scan ----
                if (wid < nb) {
                    const int j = s_q[wid];
                    const uint4* mrow = (const uint4*)(g_mat + j * N);
                    const uint4* prow = (const uint4*)s_pshift;
                    unsigned m1 = 0xffffffffu, m2 = 0xffffffffu;
                    #pragma unroll
                    for (int k = 0; k < 8; ++k) {
                        const int q = k * 32 + lane;
                        const uint4 d = mrow[q];
                        const uint4 p = prow[q];
                        unsigned tt;
                        tt = __viaddmax_u32(d.x, p.x, m1); m1 = __viaddmin_u32(d.x, p.x, m1); m2 = min(m2, tt);
                        tt = __viaddmax_u32(d.y, p.y, m1); m1 = __viaddmin_u32(d.y, p.y, m1); m2 = min(m2, tt);
                        tt = __viaddmax_u32(d.z, p.z, m1); m1 = __viaddmin_u32(d.z, p.z, m1); m2 = min(m2, tt);
                        tt = __viaddmax_u32(d.w, p.w, m1); m1 = __viaddmin_u32(d.w, p.w, m1); m2 = min(m2, tt);
                    }
                    #pragma unroll
                    for (int o = 16; o; o >>= 1) {
                        const unsigned om1 = __shfl_xor_sync(~0u, m1, o);
                        const unsigned om2 = __shfl_xor_sync(~0u, m2, o);
                        const unsigned tt  = max(m1, om1);
                        m1 = min(m1, om1);
                        m2 = min(m2, min(om2, tt));
                    }
                    if (lane == 0) {
                        const unsigned i1 = m1 & 1023u;
                        const unsigned c1 = m1 >> 10, c2 = m2 >> 10;
                        const unsigned p1 = s_pshift[i1] >> 10;
                        const unsigned long long pnew = (unsigned long long)
                            min(p1 + (c2 - c1) + eps, 4190000u);
                        atomicMax(&s_slot[i1], (pnew << 32) | (unsigned)j);
                    }
                }
            } else {
                // ---- tail path: wpb warps share one bidder's row ----
                const int b  = wid / wpb;             // bidder slot
                const int sl = wid % wpb;             // slice
                if (b < nb) {
                    const int j = s_q[b];
                    const uint4* mrow = (const uint4*)(g_mat + j * N);
                    const uint4* prow = (const uint4*)s_pshift;
                    const int base = sl * (256 / wpb);
                    unsigned m1 = 0xffffffffu, m2 = 0xffffffffu;
                    for (int k = 0; k < 8 / wpb; ++k) {
                        const int q = base + k * 32 + lane;
                        const uint4 d = mrow[q];
                        const uint4 p = prow[q];
                        unsigned tt;
                        tt = __viaddmax_u32(d.x, p.x, m1); m1 = __viaddmin_u32(d.x, p.x, m1); m2 = min(m2, tt);
                        tt = __viaddmax_u32(d.y, p.y, m1); m1 = __viaddmin_u32(d.y, p.y, m1); m2 = min(m2, tt);
                        tt = __viaddmax_u32(d.z, p.z, m1); m1 = __viaddmin_u32(d.z, p.z, m1); m2 = min(m2, tt);
                        tt = __viaddmax_u32(d.w, p.w, m1); m1 = __viaddmin_u32(d.w, p.w, m1); m2 = min(m2, tt);
                    }
                    #pragma unroll
                    for (int o = 16; o; o >>= 1) {
                        const unsigned om1 = __shfl_xor_sync(~0u, m1, o);
                        const unsigned om2 = __shfl_xor_sync(~0u, m2, o);
                        const unsigned tt  = max(m1, om1);
                        m1 = min(m1, om1);
                        m2 = min(m2, min(om2, tt));
                    }
                    if (lane == 0) { s_m1[wid] = m1; s_m2[wid] = m2; }
                }
                __syncthreads();
                // merge slices (lead warp of each bidder) and bid
                if (b < nb && sl == 0) {
                    const int j = s_q[b];
                    unsigned m1 = (lane < wpb) ? s_m1[wid + lane] : 0xffffffffu;
                    unsigned m2 = (lane < wpb) ? s_m2[wid + lane] : 0xffffffffu;
                    for (int o = wpb >> 1; o; o >>= 1) {
                        const unsigned om1 = __shfl_xor_sync(~0u, m1, o);
                        const unsigned om2 = __shfl_xor_sync(~0u, m2, o);
                        const unsigned tt  = max(m1, om1);
                        m1 = min(m1, om1);
                        m2 = min(m2, min(om2, tt));
                    }
                    if (lane == 0) {
                        const unsigned i1 = m1 & 1023u;
                        const unsigned c1 = m1 >> 10, c2 = m2 >> 10;
                        const unsigned p1 = s_pshift[i1] >> 10;
                        const unsigned long long pnew = (unsigned long long)
                            min(p1 + (c2 - c1) + eps, 4190000u);
                        atomicMax(&s_slot[i1], (pnew << 32) | (unsigned)j);
                    }
                }
            }
            __syncthreads();

            // ---- resolve: one object per thread ----
            {
                const unsigned long long s = s_slot[t];
                if (s) {
                    const int j = (int)(s & 0xffffffffull);
                    const int prev = s_owner[t];
                    if (prev >= 0) s_objof[prev] = -1;
                    s_owner[t] = (short)j;
                    s_objof[j] = (short)t;
                    s_pshift[t] = ((unsigned)(s >> 32)) << 10;
                    s_slot[t] = 0ull;
                }
            }
            __syncthreads();

            // ---- rebuild unassigned queue (index order => deterministic) ----
            const bool un = (s_objof[t] < 0);
            const unsigned bal = __ballot_sync(~0u, un);
            if (lane == 0) s_wcnt[wid] = __popc(bal);
            __syncthreads();
            if (wid == 0) {
                const int c = s_wcnt[lane];
                int inc = c;
                #pragma unroll
                for (int o = 1; o < 32; o <<= 1) {
                    const int vv = __shfl_up_sync(~0u, inc, o);
                    if (lane >= o) inc += vv;
                }
                s_wpre[lane] = inc - c;
                if (lane == 31) s_nq = inc;
            }
            __syncthreads();
            if (un)
                s_q[s_wpre[wid] + __popc(bal & ((1u << lane) - 1u))] =
                    (unsigned short)t;
            __syncthreads();
        }
        eps >>= 2;
    }

    // deterministic greedy completion (only if round cap hit; normally no-op)
    if (t == 0 && s_nq > 0) {
        for (int j = 0; j < N; ++j) if (s_objof[j] < 0) {
            for (int i = 0; i < N; ++i) if (s_owner[i] < 0) {
                s_owner[i] = (short)j; s_objof[j] = (short)i; break;
            }
        }
    }
    __syncthreads();

    // ---- exact mean of matched distances (fp32 matrix) ----
    float acc = g_dist[t * N + (int)s_objof[t]];
    #pragma unroll
    for (int o2 = 16; o2; o2 >>= 1) acc += __shfl_down_sync(~0u, acc, o2);
    if (lane == 0) s_sum[wid] = acc;
    __syncthreads();
    if (t == 0) {
        float s = 0.0f;
        #pragma unroll
        for (int w = 0; w < NW; ++w) s += s_sum[w];
        out[0] = s * (1.0f / (float)N);
    }
}

extern "C" void kernel_launch(void* const* d_in, const int* in_sizes, int n_in,
                              void* d_out, int out_size) {
    const float* gt  = (const float*)d_in[0];   // (1,1024,3) fp32
    const float* gen = (const float*)d_in[1];   // (1,1024,3) fp32
    (void)in_sizes; (void)n_in; (void)out_size;
    dist_kernel<<<(N * N) / 256, 256>>>(gt, gen);
    quant_kernel<<<(N * N) / 256, 256>>>();
    emd_auction_kernel<<<1, T>>>((float*)d_out);
}

// round 16
// speedup vs baseline: 1.3571x; 1.3571x over previous
#include <cuda_runtime.h>

#define N   1024
#define T   1024
#define NW  32
#define RCAP 30000

__device__ float    g_dist[N * N];   // exact fp32 distances (final mean)
__device__ unsigned g_mat[N * N];    // (d20 << 10) | col_index
__device__ unsigned g_dmax = 0;      // bits of max distance (positive floats)

// ---- pass 1: exact distances + global max (block-reduced atomic) ----
__global__ void dist_kernel(const float* __restrict__ gt,
                            const float* __restrict__ gen) {
    __shared__ unsigned s_wmax[8];
    const int id = blockIdx.x * blockDim.x + threadIdx.x;
    const int j = id >> 10, i = id & (N - 1);
    const float dx = gen[3 * j]     - gt[3 * i];
    const float dy = gen[3 * j + 1] - gt[3 * i + 1];
    const float dz = gen[3 * j + 2] - gt[3 * i + 2];
    const float d = sqrtf(fmaf(dx, dx, fmaf(dy, dy, dz * dz)));
    g_dist[id] = d;
    unsigned m = __reduce_max_sync(~0u, __float_as_uint(d));  // d>=0: uint==float order
    const int lane = threadIdx.x & 31, wid = threadIdx.x >> 5;
    if (lane == 0) s_wmax[wid] = m;
    __syncthreads();
    if (threadIdx.x < 8) {
        m = s_wmax[threadIdx.x];
        #pragma unroll
        for (int o = 4; o; o >>= 1) m = max(m, __shfl_xor_sync(0xffu, m, o));
        if (threadIdx.x == 0) atomicMax(&g_dmax, m);
    }
}

// ---- pass 2: quantize to 20 bits, pack column index in low 10 bits ----
__global__ void quant_kernel() {
    const int id = blockIdx.x * blockDim.x + threadIdx.x;
    const float dmax = __uint_as_float(g_dmax);
    const float scale = 1048000.0f / dmax;
    const unsigned dq = __float2uint_rn(g_dist[id] * scale);   // <= 1048000
    g_mat[id] = (dq << 10) | (unsigned)(id & (N - 1));
}

// Auction with integer eps-scaling (R12 structure: <=32 fresh-price bidders
// per round, full restart per phase). Scan = fused viadd-min/max top-2 on
// packed keys; bids via u64 atomicMax (order-independent => deterministic).
// 6 phases: eps 49152 -> 48 (/4).
__global__ __launch_bounds__(T, 1)
void emd_auction_kernel(float* __restrict__ out) {
    __shared__ __align__(16) unsigned s_pshift[N];    // price << 10
    __shared__ unsigned long long s_slot[N];          // (pnew<<32 | bidder)
    __shared__ short  s_owner[N];                     // object -> bidder (-1 free)
    __shared__ short  s_objof[N];                     // bidder -> object (-1 free)
    __shared__ unsigned short s_q[N];                 // unassigned bidders (sorted)
    __shared__ int    s_wcnt[NW], s_wpre[NW];
    __shared__ int    s_nq;
    __shared__ float  s_sum[NW];

    const int t = threadIdx.x, lane = t & 31, wid = t >> 5;

    s_pshift[t] = 0u;
    s_slot[t]   = 0ull;
    s_objof[t]  = -1;
    s_owner[t]  = -1;
    __syncthreads();

    int rounds = 0;
    unsigned eps = 49152u;                            // /4 per phase -> 48

    for (int phase = 0; phase < 6; ++phase) {
        // reset assignment, keep prices
        s_owner[t] = -1; s_objof[t] = -1;
        s_q[t] = (unsigned short)t;
        if (t == 0) s_nq = N;
        __syncthreads();

        while (s_nq > 0 && rounds < RCAP) {
            ++rounds;
            const int nb = min(s_nq, NW);

            // ---- bidding: warp w = bidder s_q[w] (fresh prices) ----
            if (wid < nb) {
                const int j = s_q[wid];
                const uint4* mrow = (const uint4*)(g_mat + j * N);
                const uint4* prow = (const uint4*)s_pshift;
                unsigned m1 = 0xffffffffu, m2 = 0xffffffffu;
                #pragma unroll
                for (int k = 0; k < 8; ++k) {
                    const int q = k * 32 + lane;
                    const uint4 d = mrow[q];
                    const uint4 p = prow[q];
                    unsigned tt;
                    tt = __viaddmax_u32(d.x, p.x, m1); m1 = __viaddmin_u32(d.x, p.x, m1); m2 = min(m2, tt);
                    tt = __viaddmax_u32(d.y, p.y, m1); m1 = __viaddmin_u32(d.y, p.y, m1); m2 = min(m2, tt);
                    tt = __viaddmax_u32(d.z, p.z, m1); m1 = __viaddmin_u32(d.z, p.z, m1); m2 = min(m2, tt);
                    tt = __viaddmax_u32(d.w, p.w, m1); m1 = __viaddmin_u32(d.w, p.w, m1); m2 = min(m2, tt);
                }
                #pragma unroll
                for (int o = 16; o; o >>= 1) {        // warp top-2 reduce
                    const unsigned om1 = __shfl_xor_sync(~0u, m1, o);
                    const unsigned om2 = __shfl_xor_sync(~0u, m2, o);
                    const unsigned tt  = max(m1, om1);
                    m1 = min(m1, om1);
                    m2 = min(m2, min(om2, tt));
                }
                if (lane == 0) {
                    const unsigned i1 = m1 & 1023u;
                    const unsigned c1 = m1 >> 10, c2 = m2 >> 10;
                    const unsigned p1 = s_pshift[i1] >> 10;
                    const unsigned long long pnew = (unsigned long long)
                        min(p1 + (c2 - c1) + eps, 4190000u);
                    atomicMax(&s_slot[i1], (pnew << 32) | (unsigned)j);
                }
            }
            __syncthreads();

            // ---- resolve: one object per thread ----
            {
                const unsigned long long s = s_slot[t];
                if (s) {
                    const int j = (int)(s & 0xffffffffull);
                    const int prev = s_owner[t];
                    if (prev >= 0) s_objof[prev] = -1;
                    s_owner[t] = (short)j;
                    s_objof[j] = (short)t;
                    s_pshift[t] = ((unsigned)(s >> 32)) << 10;
                    s_slot[t] = 0ull;
                }
            }
            __syncthreads();

            // ---- rebuild unassigned queue (index order => deterministic) ----
            const bool un = (s_objof[t] < 0);
            const unsigned bal = __ballot_sync(~0u, un);
            if (lane == 0) s_wcnt[wid] = __popc(bal);
            __syncthreads();
            if (wid == 0) {
                const int c = s_wcnt[lane];
                int inc = c;
                #pragma unroll
                for (int o = 1; o < 32; o <<= 1) {
                    const int vv = __shfl_up_sync(~0u, inc, o);
                    if (lane >= o) inc += vv;
                }
                s_wpre[lane] = inc - c;
                if (lane == 31) s_nq = inc;
            }
            __syncthreads();
            if (un)
                s_q[s_wpre[wid] + __popc(bal & ((1u << lane) - 1u))] =
                    (unsigned short)t;
            __syncthreads();
        }
        eps >>= 2;
    }

    // deterministic greedy completion (only if round cap hit; normally no-op)
    if (t == 0 && s_nq > 0) {
        for (int j = 0; j < N; ++j) if (s_objof[j] < 0) {
            for (int i = 0; i < N; ++i) if (s_owner[i] < 0) {
                s_owner[i] = (short)j; s_objof[j] = (short)i; break;
            }
        }
    }
    __syncthreads();

    // ---- exact mean of matched distances (fp32 matrix) ----
    float acc = g_dist[t * N + (int)s_objof[t]];
    #pragma unroll
    for (int o2 = 16; o2; o2 >>= 1) acc += __shfl_down_sync(~0u, acc, o2);
    if (lane == 0) s_sum[wid] = acc;
    __syncthreads();
    if (t == 0) {
        float s = 0.0f;
        #pragma unroll
        for (int w = 0; w < NW; ++w) s += s_sum[w];
        out[0] = s * (1.0f / (float)N);
    }
}

extern "C" void kernel_launch(void* const* d_in, const int* in_sizes, int n_in,
                              void* d_out, int out_size) {
    const float* gt  = (const float*)d_in[0];   // (1,1024,3) fp32
    const float* gen = (const float*)d_in[1];   // (1,1024,3) fp32
    (void)in_sizes; (void)n_in; (void)out_size;
    dist_kernel<<<(N * N) / 256, 256>>>(gt, gen);
    quant_kernel<<<(N * N) / 256, 256>>>();
    emd_auction_kernel<<<1, T>>>((float*)d_out);
}

// round 17
// speedup vs baseline: 1.4528x; 1.0705x over previous
#include <cuda_runtime.h>

#define N   1024
#define T   1024
#define NW  32
#define RCAP 30000

__device__ float    g_dist[N * N];   // exact fp32 distances (final mean)
__device__ unsigned g_mat[N * N];    // (d20 << 10) | col_index
__device__ unsigned g_dmax = 0;      // bits of max distance (positive floats)

// ---- pass 1: exact distances + global max (block-reduced atomic) ----
__global__ void dist_kernel(const float* __restrict__ gt,
                            const float* __restrict__ gen) {
    __shared__ unsigned s_wmax[8];
    const int id = blockIdx.x * blockDim.x + threadIdx.x;
    const int j = id >> 10, i = id & (N - 1);
    const float dx = gen[3 * j]     - gt[3 * i];
    const float dy = gen[3 * j + 1] - gt[3 * i + 1];
    const float dz = gen[3 * j + 2] - gt[3 * i + 2];
    const float d = sqrtf(fmaf(dx, dx, fmaf(dy, dy, dz * dz)));
    g_dist[id] = d;
    unsigned m = __reduce_max_sync(~0u, __float_as_uint(d));  // d>=0: uint==float order
    const int lane = threadIdx.x & 31, wid = threadIdx.x >> 5;
    if (lane == 0) s_wmax[wid] = m;
    __syncthreads();
    if (threadIdx.x < 8) {
        m = s_wmax[threadIdx.x];
        #pragma unroll
        for (int o = 4; o; o >>= 1) m = max(m, __shfl_xor_sync(0xffu, m, o));
        if (threadIdx.x == 0) atomicMax(&g_dmax, m);
    }
}

// ---- pass 2: quantize to 20 bits, pack column index in low 10 bits ----
__global__ void quant_kernel() {
    const int id = blockIdx.x * blockDim.x + threadIdx.x;
    const float dmax = __uint_as_float(g_dmax);
    const float scale = 1048000.0f / dmax;
    const unsigned dq = __float2uint_rn(g_dist[id] * scale);   // <= 1048000
    g_mat[id] = (dq << 10) | (unsigned)(id & (N - 1));
}

// Auction with integer eps-scaling (<=32 fresh-price bidders per round,
// full restart per phase). Scan = fused viadd-min/max top-2 on packed keys;
// bids via u64 atomicMax (order-independent => deterministic).
// 5 phases: eps 49152 -> 192 (/4).
__global__ __launch_bounds__(T, 1)
void emd_auction_kernel(float* __restrict__ out) {
    __shared__ __align__(16) unsigned s_pshift[N];    // price << 10
    __shared__ unsigned long long s_slot[N];          // (pnew<<32 | bidder)
    __shared__ short  s_owner[N];                     // object -> bidder (-1 free)
    __shared__ short  s_objof[N];                     // bidder -> object (-1 free)
    __shared__ unsigned short s_q[N];                 // unassigned bidders (sorted)
    __shared__ int    s_wcnt[NW], s_wpre[NW];
    __shared__ int    s_nq;
    __shared__ float  s_sum[NW];

    const int t = threadIdx.x, lane = t & 31, wid = t >> 5;

    s_pshift[t] = 0u;
    s_slot[t]   = 0ull;
    s_objof[t]  = -1;
    s_owner[t]  = -1;
    __syncthreads();

    int rounds = 0;
    unsigned eps = 49152u;                            // /4 per phase -> 192

    for (int phase = 0; phase < 5; ++phase) {
        // reset assignment, keep prices
        s_owner[t] = -1; s_objof[t] = -1;
        s_q[t] = (unsigned short)t;
        if (t == 0) s_nq = N;
        __syncthreads();

        while (s_nq > 0 && rounds < RCAP) {
            ++rounds;
            const int nb = min(s_nq, NW);

            // ---- bidding: warp w = bidder s_q[w] (fresh prices) ----
            if (wid < nb) {
                const int j = s_q[wid];
                const uint4* mrow = (const uint4*)(g_mat + j * N);
                const uint4* prow = (const uint4*)s_pshift;
                unsigned m1 = 0xffffffffu, m2 = 0xffffffffu;
                #pragma unroll
                for (int k = 0; k < 8; ++k) {
                    const int q = k * 32 + lane;
                    const uint4 d = mrow[q];
                    const uint4 p = prow[q];
                    unsigned tt;
                    tt = __viaddmax_u32(d.x, p.x, m1); m1 = __viaddmin_u32(d.x, p.x, m1); m2 = min(m2, tt);
                    tt = __viaddmax_u32(d.y, p.y, m1); m1 = __viaddmin_u32(d.y, p.y, m1); m2 = min(m2, tt);
                    tt = __viaddmax_u32(d.z, p.z, m1); m1 = __viaddmin_u32(d.z, p.z, m1); m2 = min(m2, tt);
                    tt = __viaddmax_u32(d.w, p.w, m1); m1 = __viaddmin_u32(d.w, p.w, m1); m2 = min(m2, tt);
                }
                #pragma unroll
                for (int o = 16; o; o >>= 1) {        // warp top-2 reduce
                    const unsigned om1 = __shfl_xor_sync(~0u, m1, o);
                    const unsigned om2 = __shfl_xor_sync(~0u, m2, o);
                    const unsigned tt  = max(m1, om1);
                    m1 = min(m1, om1);
                    m2 = min(m2, min(om2, tt));
                }
                if (lane == 0) {
                    const unsigned i1 = m1 & 1023u;
                    const unsigned c1 = m1 >> 10, c2 = m2 >> 10;
                    const unsigned p1 = s_pshift[i1] >> 10;
                    const unsigned long long pnew = (unsigned long long)
                        min(p1 + (c2 - c1) + eps, 4190000u);
                    atomicMax(&s_slot[i1], (pnew << 32) | (unsigned)j);
                }
            }
            __syncthreads();

            // ---- resolve: one object per thread ----
            {
                const unsigned long long s = s_slot[t];
                if (s) {
                    const int j = (int)(s & 0xffffffffull);
                    const int prev = s_owner[t];
                    if (prev >= 0) s_objof[prev] = -1;
                    s_owner[t] = (short)j;
                    s_objof[j] = (short)t;
                    s_pshift[t] = ((unsigned)(s >> 32)) << 10;
                    s_slot[t] = 0ull;
                }
            }
            __syncthreads();

            // ---- rebuild unassigned queue (index order => deterministic) ----
            const bool un = (s_objof[t] < 0);
            const unsigned bal = __ballot_sync(~0u, un);
            if (lane == 0) s_wcnt[wid] = __popc(bal);
            __syncthreads();
            if (wid == 0) {
                const int c = s_wcnt[lane];
                int inc = c;
                #pragma unroll
                for (int o = 1; o < 32; o <<= 1) {
                    const int vv = __shfl_up_sync(~0u, inc, o);
                    if (lane >= o) inc += vv;
                }
                s_wpre[lane] = inc - c;
                if (lane == 31) s_nq = inc;
            }
            __syncthreads();
            if (un)
                s_q[s_wpre[wid] + __popc(bal & ((1u << lane) - 1u))] =
                    (unsigned short)t;
            __syncthreads();
        }
        eps >>= 2;
    }

    // deterministic greedy completion (only if round cap hit; normally no-op)
    if (t == 0 && s_nq > 0) {
        for (int j = 0; j < N; ++j) if (s_objof[j] < 0) {
            for (int i = 0; i < N; ++i) if (s_owner[i] < 0) {
                s_owner[i] = (short)j; s_objof[j] = (short)i; break;
            }
        }
    }
    __syncthreads();

    // ---- exact mean of matched distances (fp32 matrix) ----
    float acc = g_dist[t * N + (int)s_objof[t]];
    #pragma unroll
    for (int o2 = 16; o2; o2 >>= 1) acc += __shfl_down_sync(~0u, acc, o2);
    if (lane == 0) s_sum[wid] = acc;
    __syncthreads();
    if (t == 0) {
        float s = 0.0f;
        #pragma unroll
        for (int w = 0; w < NW; ++w) s += s_sum[w];
        out[0] = s * (1.0f / (float)N);
    }
}

extern "C" void kernel_launch(void* const* d_in, const int* in_sizes, int n_in,
                              void* d_out, int out_size) {
    const float* gt  = (const float*)d_in[0];   // (1,1024,3) fp32
    const float* gen = (const float*)d_in[1];   // (1,1024,3) fp32
    (void)in_sizes; (void)n_in; (void)out_size;
    dist_kernel<<<(N * N) / 256, 256>>>(gt, gen);
    quant_kernel<<<(N * N) / 256, 256>>>();
    emd_auction_kernel<<<1, T>>>((float*)d_out);
}